// round 3
// baseline (speedup 1.0000x reference)
#include <cuda_runtime.h>

#define C_IN  128
#define C_OUT 256
#define HW    56
#define IMG   (HW * HW)        /* 3136  */
#define NIMG  32
#define NPIX  (NIMG * IMG)     /* 100352 = 784 * 128 */

// Transposed weights: [tap=r*3+s][ic][oc], oc contiguous for coalesced tile loads.
__device__ float g_wt[9 * C_IN * C_OUT];

__global__ void wt_transpose_kernel(const float* __restrict__ w) {
    int i = blockIdx.x * 256 + threadIdx.x;        // over 256*128*9 = 294912
    if (i < C_OUT * C_IN * 9) {
        int oc  = i / (C_IN * 9);
        int rem = i - oc * (C_IN * 9);
        int ic  = rem / 9;
        int tap = rem - ic * 9;
        g_wt[(tap * C_IN + ic) * C_OUT + oc] = w[i];
    }
}

// Implicit-GEMM conv: C[oc][pix] = sum_{tap,ic} Wt[tap][ic][oc] * im2col(x)
// Block tile: 128 oc x 128 pix, K-chunk 8, double-buffered, 8x8 thread tile.
__global__ __launch_bounds__(256, 2)
void conv_kernel(const float* __restrict__ x,
                 const float* __restrict__ bias,
                 float* __restrict__ out) {
    __shared__ float As[2][8][128];   // [k][oc]
    __shared__ float Bs[2][8][128];   // [k][pix]

    const int tid = threadIdx.x;
    const int tx  = tid & 15;         // pixel-frag group
    const int ty  = tid >> 4;         // oc-frag group
    const int ocBase  = blockIdx.y * 128;
    const int pixBase = blockIdx.x * 128;

    // ---- B-tile (input) load mapping: thread -> (pixel pl, 4 consecutive ic rows)
    const int pl = tid & 127;
    const int kg = (tid >> 7) * 4;            // 0 or 4
    const int pg   = pixBase + pl;
    const int bimg = pg / IMG;
    const int prem = pg - bimg * IMG;
    const int oh   = prem / HW;
    const int ow   = prem - oh * HW;
    const long xb  = (long)bimg * C_IN * IMG;

    // ---- A-tile (weight) load mapping: thread -> one float4
    const int arow = tid >> 5;                // k row 0..7
    const int acol = (tid & 31) << 2;         // oc col 0..124

    float acc[8][8];
    #pragma unroll
    for (int i = 0; i < 8; ++i)
        #pragma unroll
        for (int j = 0; j < 8; ++j) acc[i][j] = 0.f;

    // ---- prologue: stage 0 (tap 0: r=0,s=0 ; icB=0) ----
    {
        const int ih = oh - 1, iw = ow - 1;
        const bool ok = ((unsigned)ih < (unsigned)HW) && ((unsigned)iw < (unsigned)HW);
        const float* src = x + xb + (long)kg * IMG + ih * HW + iw;
        #pragma unroll
        for (int kk = 0; kk < 4; ++kk)
            Bs[0][kg + kk][pl] = ok ? src[kk * IMG] : 0.f;
        *(float4*)&As[0][arow][acol] =
            *(const float4*)(g_wt + (long)arow * C_OUT + ocBase + acol);
    }
    __syncthreads();

    const int NSTAGE = 9 * 16;   // 9 taps * (128 ic / 8)
    for (int s = 0; s < NSTAGE; ++s) {
        const int cbuf = s & 1;

        // ---- prefetch next stage gmem -> regs ----
        float4 aNext;
        float bN0, bN1, bN2, bN3;
        if (s + 1 < NSTAGE) {
            const int sn  = s + 1;
            const int tap = sn >> 4;
            const int icB = (sn & 15) << 3;
            const int r   = tap / 3;
            const int sc  = tap - r * 3;
            const int ih = oh + r - 1, iw = ow + sc - 1;
            const bool ok = ((unsigned)ih < (unsigned)HW) && ((unsigned)iw < (unsigned)HW);
            const float* src = x + xb + (long)(icB + kg) * IMG + ih * HW + iw;
            bN0 = ok ? src[0 * IMG] : 0.f;
            bN1 = ok ? src[1 * IMG] : 0.f;
            bN2 = ok ? src[2 * IMG] : 0.f;
            bN3 = ok ? src[3 * IMG] : 0.f;
            aNext = *(const float4*)(g_wt + (long)(tap * C_IN + icB + arow) * C_OUT
                                     + ocBase + acol);
        }

        // ---- compute current stage ----
        #pragma unroll
        for (int k = 0; k < 8; ++k) {
            float4 a0 = *(const float4*)&As[cbuf][k][ty * 4];
            float4 a1 = *(const float4*)&As[cbuf][k][64 + ty * 4];
            float4 b0 = *(const float4*)&Bs[cbuf][k][tx * 4];
            float4 b1 = *(const float4*)&Bs[cbuf][k][64 + tx * 4];
            float a[8] = {a0.x, a0.y, a0.z, a0.w, a1.x, a1.y, a1.z, a1.w};
            float b[8] = {b0.x, b0.y, b0.z, b0.w, b1.x, b1.y, b1.z, b1.w};
            #pragma unroll
            for (int i = 0; i < 8; ++i)
                #pragma unroll
                for (int j = 0; j < 8; ++j)
                    acc[i][j] = fmaf(a[i], b[j], acc[i][j]);
        }

        // ---- commit prefetched stage to the other buffer ----
        if (s + 1 < NSTAGE) {
            const int nbuf = (s + 1) & 1;
            Bs[nbuf][kg + 0][pl] = bN0;
            Bs[nbuf][kg + 1][pl] = bN1;
            Bs[nbuf][kg + 2][pl] = bN2;
            Bs[nbuf][kg + 3][pl] = bN3;
            *(float4*)&As[nbuf][arow][acol] = aNext;
        }
        __syncthreads();
    }

    // ---- epilogue: bias + float4 stores (3136 % 4 == 0, no image split in a float4) ----
    #pragma unroll
    for (int half_i = 0; half_i < 2; ++half_i) {
        #pragma unroll
        for (int ii = 0; ii < 4; ++ii) {
            const int oc = ocBase + half_i * 64 + ty * 4 + ii;
            const float bv = bias[oc];
            #pragma unroll
            for (int half_j = 0; half_j < 2; ++half_j) {
                const int p0  = pixBase + half_j * 64 + tx * 4;
                const int bo  = p0 / IMG;
                const int rem = p0 - bo * IMG;
                float4 v;
                v.x = acc[half_i * 4 + ii][half_j * 4 + 0] + bv;
                v.y = acc[half_i * 4 + ii][half_j * 4 + 1] + bv;
                v.z = acc[half_i * 4 + ii][half_j * 4 + 2] + bv;
                v.w = acc[half_i * 4 + ii][half_j * 4 + 3] + bv;
                *(float4*)&out[((long)bo * C_OUT + oc) * IMG + rem] = v;
            }
        }
    }
}

extern "C" void kernel_launch(void* const* d_in, const int* in_sizes, int n_in,
                              void* d_out, int out_size) {
    const float* x    = (const float*)d_in[0];   // [32,128,56,56]
    const float* w    = (const float*)d_in[1];   // [256,128,3,3]
    const float* bias = (const float*)d_in[2];   // [256]
    float* out = (float*)d_out;                  // [32,256,56,56]

    wt_transpose_kernel<<<(C_OUT * C_IN * 9 + 255) / 256, 256>>>(w);

    dim3 grid(NPIX / 128, C_OUT / 128);          // (784, 2)
    conv_kernel<<<grid, 256>>>(x, bias, out);
}

// round 6
// speedup vs baseline: 1.0764x; 1.0764x over previous
#include <cuda_runtime.h>
#include <cstdint>

#define C_IN  128
#define C_OUT 256
#define HW    56
#define IMG   (HW * HW)        /* 3136  */
#define NIMG  32
#define NPIX  (NIMG * IMG)     /* 100352 = 784 * 128 */

// Transposed weights: [tap=r*3+s][ic][oc], oc contiguous for coalesced tile loads.
__device__ float g_wt[9 * C_IN * C_OUT];

__global__ void wt_transpose_kernel(const float* __restrict__ w) {
    int i = blockIdx.x * 256 + threadIdx.x;        // over 256*128*9 = 294912
    if (i < C_OUT * C_IN * 9) {
        int oc  = i / (C_IN * 9);
        int rem = i - oc * (C_IN * 9);
        int ic  = rem / 9;
        int tap = rem - ic * 9;
        g_wt[(tap * C_IN + ic) * C_OUT + oc] = w[i];
    }
}

// Packed-fp32 helpers (sm_103a f32x2 path — full-rate fp32)
#define FFMA2(d, a, b, c) \
    asm("fma.rn.f32x2 %0, %1, %2, %3;" : "=l"(d) : "l"(a), "l"(b), "l"(c))
#define PACK2(out, lo, hi) \
    asm("mov.b64 %0, {%1, %2};" : "=l"(out) : "f"(lo), "f"(hi))
#define UNPACK2(lo, hi, in) \
    asm("mov.b64 {%0, %1}, %2;" : "=f"(lo), "=f"(hi) : "l"(in))

// Implicit-GEMM conv: C[oc][pix] = sum_{tap,ic} Wt[tap][ic][oc] * im2col(x)
// Block tile: 128 oc x 128 pix, K-chunk 8, double-buffered, 8x8 thread tile
// computed as 8 x (4 x f32x2) packed accumulators.
__global__ __launch_bounds__(256, 2)
void conv_kernel(const float* __restrict__ x,
                 const float* __restrict__ bias,
                 float* __restrict__ out) {
    __shared__ float As[2][8][128];   // [k][oc]
    __shared__ float Bs[2][8][128];   // [k][pix]

    const int tid = threadIdx.x;
    const int tx  = tid & 15;         // pixel-frag group
    const int ty  = tid >> 4;         // oc-frag group
    const int ocBase  = blockIdx.y * 128;
    const int pixBase = blockIdx.x * 128;

    // ---- B-tile (input) load mapping: thread -> (pixel pl, 4 consecutive ic rows)
    const int pl = tid & 127;
    const int kg = (tid >> 7) * 4;            // 0 or 4
    const int pg   = pixBase + pl;
    const int bimg = pg / IMG;
    const int prem = pg - bimg * IMG;
    const int oh   = prem / HW;
    const int ow   = prem - oh * HW;
    const long xb  = (long)bimg * C_IN * IMG;

    // ---- A-tile (weight) load mapping: thread -> one float4
    const int arow = tid >> 5;                // k row 0..7
    const int acol = (tid & 31) << 2;         // oc col 0..124

    // Packed accumulators: acc2[i][jp] holds columns (2*jp, 2*jp+1) of the
    // 8-wide pixel frag (jp 0..1 -> first half, jp 2..3 -> second half).
    uint64_t acc2[8][4];
    #pragma unroll
    for (int i = 0; i < 8; ++i)
        #pragma unroll
        for (int j = 0; j < 4; ++j) acc2[i][j] = 0ull;

    // ---- prologue: stage 0 (tap 0: r=0,s=0 ; icB=0) ----
    {
        const int ih = oh - 1, iw = ow - 1;
        const bool ok = ((unsigned)ih < (unsigned)HW) && ((unsigned)iw < (unsigned)HW);
        const float* src = x + xb + (long)kg * IMG + ih * HW + iw;
        #pragma unroll
        for (int kk = 0; kk < 4; ++kk)
            Bs[0][kg + kk][pl] = ok ? src[kk * IMG] : 0.f;
        *(float4*)&As[0][arow][acol] =
            *(const float4*)(g_wt + (long)arow * C_OUT + ocBase + acol);
    }
    __syncthreads();

    const int NSTAGE = 9 * 16;   // 9 taps * (128 ic / 8)
    for (int s = 0; s < NSTAGE; ++s) {
        const int cbuf = s & 1;

        // ---- prefetch next stage gmem -> regs ----
        float4 aNext;
        float bN0, bN1, bN2, bN3;
        if (s + 1 < NSTAGE) {
            const int sn  = s + 1;
            const int tap = sn >> 4;
            const int icB = (sn & 15) << 3;
            const int r   = tap / 3;
            const int sc  = tap - r * 3;
            const int ih = oh + r - 1, iw = ow + sc - 1;
            const bool ok = ((unsigned)ih < (unsigned)HW) && ((unsigned)iw < (unsigned)HW);
            const float* src = x + xb + (long)(icB + kg) * IMG + ih * HW + iw;
            bN0 = ok ? src[0 * IMG] : 0.f;
            bN1 = ok ? src[1 * IMG] : 0.f;
            bN2 = ok ? src[2 * IMG] : 0.f;
            bN3 = ok ? src[3 * IMG] : 0.f;
            aNext = *(const float4*)(g_wt + (long)(tap * C_IN + icB + arow) * C_OUT
                                     + ocBase + acol);
        }

        // ---- compute current stage (packed f32x2 FMAs) ----
        #pragma unroll
        for (int k = 0; k < 8; ++k) {
            float4 a0 = *(const float4*)&As[cbuf][k][ty * 4];
            float4 a1 = *(const float4*)&As[cbuf][k][64 + ty * 4];
            float4 b0 = *(const float4*)&Bs[cbuf][k][tx * 4];
            float4 b1 = *(const float4*)&Bs[cbuf][k][64 + tx * 4];

            uint64_t bp[4];
            PACK2(bp[0], b0.x, b0.y);
            PACK2(bp[1], b0.z, b0.w);
            PACK2(bp[2], b1.x, b1.y);
            PACK2(bp[3], b1.z, b1.w);

            float a[8] = {a0.x, a0.y, a0.z, a0.w, a1.x, a1.y, a1.z, a1.w};
            #pragma unroll
            for (int i = 0; i < 8; ++i) {
                uint64_t ap;
                PACK2(ap, a[i], a[i]);
                #pragma unroll
                for (int j = 0; j < 4; ++j)
                    FFMA2(acc2[i][j], ap, bp[j], acc2[i][j]);
            }
        }

        // ---- commit prefetched stage to the other buffer ----
        if (s + 1 < NSTAGE) {
            const int nbuf = (s + 1) & 1;
            Bs[nbuf][kg + 0][pl] = bN0;
            Bs[nbuf][kg + 1][pl] = bN1;
            Bs[nbuf][kg + 2][pl] = bN2;
            Bs[nbuf][kg + 3][pl] = bN3;
            *(float4*)&As[nbuf][arow][acol] = aNext;
        }
        __syncthreads();
    }

    // ---- epilogue: bias + float4 stores (3136 % 4 == 0, no image split in a float4) ----
    #pragma unroll
    for (int half_i = 0; half_i < 2; ++half_i) {
        #pragma unroll
        for (int ii = 0; ii < 4; ++ii) {
            const int row = half_i * 4 + ii;
            const int oc  = ocBase + half_i * 64 + ty * 4 + ii;
            const float bv = bias[oc];
            #pragma unroll
            for (int half_j = 0; half_j < 2; ++half_j) {
                const int p0  = pixBase + half_j * 64 + tx * 4;
                const int bo  = p0 / IMG;
                const int rem = p0 - bo * IMG;
                float4 v;
                UNPACK2(v.x, v.y, acc2[row][half_j * 2 + 0]);
                UNPACK2(v.z, v.w, acc2[row][half_j * 2 + 1]);
                v.x += bv; v.y += bv; v.z += bv; v.w += bv;
                *(float4*)&out[((long)bo * C_OUT + oc) * IMG + rem] = v;
            }
        }
    }
}

extern "C" void kernel_launch(void* const* d_in, const int* in_sizes, int n_in,
                              void* d_out, int out_size) {
    const float* x    = (const float*)d_in[0];   // [32,128,56,56]
    const float* w    = (const float*)d_in[1];   // [256,128,3,3]
    const float* bias = (const float*)d_in[2];   // [256]
    float* out = (float*)d_out;                  // [32,256,56,56]

    wt_transpose_kernel<<<(C_OUT * C_IN * 9 + 255) / 256, 256>>>(w);

    dim3 grid(NPIX / 128, C_OUT / 128);          // (784, 2)
    conv_kernel<<<grid, 256>>>(x, bias, out);
}

// round 11
// speedup vs baseline: 1.8385x; 1.7080x over previous
#include <cuda_runtime.h>
#include <cuda_bf16.h>
#include <cstdint>

#define C_IN   128
#define C_OUT  256
#define HW     56
#define IMG    3136
#define NIMG   32
#define NPIX   100352
#define KTOT   1152          /* 9 taps * 128 ic */
#define NSTAGE 36            /* 9 taps * 4 (32-ic quarters) */
#define ROWB   80            /* smem row stride: 64B data + 16B skew (conflict-free LDSM) */

// ---------------- device scratch (alloc-free) ----------------
__device__ __nv_bfloat16 g_xhi[(size_t)NPIX * C_IN];   // NHWC hi
__device__ __nv_bfloat16 g_xlo[(size_t)NPIX * C_IN];   // NHWC lo
__device__ __nv_bfloat16 g_whi[C_OUT * KTOT];          // [oc][tap][ic] hi
__device__ __nv_bfloat16 g_wlo[C_OUT * KTOT];          // [oc][tap][ic] lo

// ---------------- PTX helpers (base PTX only: sm_80-level, OK on sm_103) ----
__device__ __forceinline__ uint32_t smem_u32(const void* p) {
    return (uint32_t)__cvta_generic_to_shared(p);
}
#define CP16(dst, src, sz) \
    asm volatile("cp.async.cg.shared.global [%0], [%1], 16, %2;" \
                 :: "r"(dst), "l"(src), "r"(sz))
#define CP_COMMIT() asm volatile("cp.async.commit_group;" ::: "memory")

#define LDSM4(r0, r1, r2, r3, a) \
    asm volatile("ldmatrix.sync.aligned.m8n8.x4.shared.b16 {%0,%1,%2,%3}, [%4];" \
                 : "=r"(r0), "=r"(r1), "=r"(r2), "=r"(r3) : "r"(a))

#define MMA(d, a, b) \
    asm volatile("mma.sync.aligned.m16n8k16.row.col.f32.bf16.bf16.f32 " \
                 "{%0,%1,%2,%3}, {%4,%5,%6,%7}, {%8,%9}, {%0,%1,%2,%3};" \
                 : "+f"((d)[0]), "+f"((d)[1]), "+f"((d)[2]), "+f"((d)[3]) \
                 : "r"((a)[0]), "r"((a)[1]), "r"((a)[2]), "r"((a)[3]), \
                   "r"((b)[0]), "r"((b)[1]))

// ---------------- SMEM layout: 3 pipeline buffers ----------------
// per stage: A hi, A lo (128 rows x 80B), B hi, B lo (128 rows x 80B) = 40960 B
#define STG_BYTES 40960
#define SA_OFF(buf, sp) ((buf) * STG_BYTES + (sp) * 10240)
#define SB_OFF(buf, sp) ((buf) * STG_BYTES + 20480 + (sp) * 10240)
#define SMEM_TOTAL (3 * STG_BYTES)

// ---------------- prep kernels ----------------
__global__ void xprep_kernel(const float* __restrict__ x) {
    __shared__ float t[C_IN][HW + 1];
    const int b = blockIdx.x, h = blockIdx.y, tid = threadIdx.x;
    const float* src = x + ((size_t)b * C_IN) * IMG + h * HW;
    for (int i = tid; i < C_IN * HW; i += 256) {
        int ic = i / HW, w = i - ic * HW;
        t[ic][w] = src[(size_t)ic * IMG + w];
    }
    __syncthreads();
    const size_t ob = ((size_t)(b * HW + h) * HW) * C_IN;
    for (int i = tid; i < HW * (C_IN / 2); i += 256) {
        int w = i / (C_IN / 2), icp = (i - w * (C_IN / 2)) * 2;
        float v0 = t[icp][w], v1 = t[icp + 1][w];
        __nv_bfloat16 h0 = __float2bfloat16(v0), h1 = __float2bfloat16(v1);
        __nv_bfloat16 l0 = __float2bfloat16(v0 - __bfloat162float(h0));
        __nv_bfloat16 l1 = __float2bfloat16(v1 - __bfloat162float(h1));
        __nv_bfloat162 ph; ph.x = h0; ph.y = h1;
        __nv_bfloat162 pl; pl.x = l0; pl.y = l1;
        *(__nv_bfloat162*)&g_xhi[ob + (size_t)w * C_IN + icp] = ph;
        *(__nv_bfloat162*)&g_xlo[ob + (size_t)w * C_IN + icp] = pl;
    }
}

__global__ void wprep_kernel(const float* __restrict__ w) {
    int i = blockIdx.x * 256 + threadIdx.x;           // dest-linear over 294912
    if (i < C_OUT * KTOT) {
        int oc = i / KTOT;
        int r = i - oc * KTOT;
        int tap = r >> 7, ic = r & 127;
        float v = w[(oc * C_IN + ic) * 9 + tap];
        __nv_bfloat16 hi = __float2bfloat16(v);
        g_whi[i] = hi;
        g_wlo[i] = __float2bfloat16(v - __bfloat162float(hi));
    }
}

// ---------------- main MMA kernel ----------------
// CTA: 128 oc x 128 pix. 8 warps as 2(m) x 4(n); warp tile 64 x 32.
__global__ __launch_bounds__(256, 1)
void conv_mma_kernel(const float* __restrict__ bias, float* __restrict__ out) {
    extern __shared__ char smem[];
    const uint32_t sb = smem_u32(smem);
    const int tid = threadIdx.x;
    const int pixBase = blockIdx.x * 128;
    const int ocBase  = blockIdx.y * 128;

    // ---- loader geometry (per thread: one smem row, one 32B half) ----
    const int lrow = tid >> 1, half = tid & 1;
    const int pg   = pixBase + lrow;
    const int pb   = pg / IMG;
    const int prem = pg - pb * IMG;
    const int poh  = prem / HW;
    const int pow_ = prem - poh * HW;
    const size_t pbase = (size_t)pb * IMG;
    const char* aHsrc = (const char*)(g_whi + (size_t)(ocBase + lrow) * KTOT + half * 16);
    const char* aLsrc = (const char*)(g_wlo + (size_t)(ocBase + lrow) * KTOT + half * 16);
    const uint32_t srowOff = (uint32_t)lrow * ROWB + half * 32;

    auto load_stage = [&](int s) {
        const int buf = s % 3;
        const int tap = s >> 2, icq = s & 3;
        const int tr = tap / 3, tc = tap - tr * 3;
        // A tiles (weights)
        {
            const char* gh = aHsrc + ((tap << 7) + (icq << 5)) * 2;
            const char* gl = aLsrc + ((tap << 7) + (icq << 5)) * 2;
            uint32_t d0 = sb + SA_OFF(buf, 0) + srowOff;
            uint32_t d1 = sb + SA_OFF(buf, 1) + srowOff;
            CP16(d0,      gh,      16);
            CP16(d0 + 16, gh + 16, 16);
            CP16(d1,      gl,      16);
            CP16(d1 + 16, gl + 16, 16);
        }
        // B tiles (im2col pixels, zero-fill halo)
        {
            const int ih = poh + tr - 1, iw = pow_ + tc - 1;
            const bool ok = ((unsigned)ih < (unsigned)HW) && ((unsigned)iw < (unsigned)HW);
            const size_t gi = ok ? (((pbase + ih * HW + iw) * C_IN) + (icq << 5) + half * 16)
                                 : 0;
            const int sz = ok ? 16 : 0;
            const char* gh = (const char*)(g_xhi + gi);
            const char* gl = (const char*)(g_xlo + gi);
            uint32_t d0 = sb + SB_OFF(buf, 0) + srowOff;
            uint32_t d1 = sb + SB_OFF(buf, 1) + srowOff;
            CP16(d0,      gh,      sz);
            CP16(d0 + 16, gh + 16, sz);
            CP16(d1,      gl,      sz);
            CP16(d1 + 16, gl + 16, sz);
        }
        CP_COMMIT();
    };

    // ---- compute geometry ----
    const int wid = tid >> 5, lane = tid & 31;
    const int warp_m = wid >> 2;          // 0..1 -> 64 oc rows
    const int warp_n = wid & 3;           // 0..3 -> 32 pix cols
    const uint32_t aLaneOff =
        (uint32_t)(warp_m * 64 + (lane & 15)) * ROWB + (lane >> 4) * 16;
    const uint32_t bLaneOff =
        (uint32_t)(warp_n * 32 + ((lane >> 4) & 1) * 8 + (lane & 7)) * ROWB +
        ((lane >> 3) & 1) * 16;

    float acc[4][4][4];
    #pragma unroll
    for (int i = 0; i < 4; ++i)
        #pragma unroll
        for (int j = 0; j < 4; ++j)
            #pragma unroll
            for (int e = 0; e < 4; ++e) acc[i][j][e] = 0.f;

    load_stage(0);
    load_stage(1);

    for (int s = 0; s < NSTAGE; ++s) {
        if (s + 2 < NSTAGE) {
            load_stage(s + 2);
            asm volatile("cp.async.wait_group 2;" ::: "memory");
        } else if (s + 1 < NSTAGE) {
            asm volatile("cp.async.wait_group 1;" ::: "memory");
        } else {
            asm volatile("cp.async.wait_group 0;" ::: "memory");
        }
        __syncthreads();

        const int buf = s % 3;
        const uint32_t aH = sb + SA_OFF(buf, 0) + aLaneOff;
        const uint32_t aL = sb + SA_OFF(buf, 1) + aLaneOff;
        const uint32_t bH = sb + SB_OFF(buf, 0) + bLaneOff;
        const uint32_t bL = sb + SB_OFF(buf, 1) + bLaneOff;

        #pragma unroll
        for (int k0 = 0; k0 < 2; ++k0) {            // two k16 steps (32B apart)
            uint32_t Ah[4][4], Al[4][4], Bh[2][4], Bl[2][4];
            #pragma unroll
            for (int mt = 0; mt < 4; ++mt) {
                LDSM4(Ah[mt][0], Ah[mt][1], Ah[mt][2], Ah[mt][3],
                      aH + mt * 16 * ROWB + k0 * 32);
                LDSM4(Al[mt][0], Al[mt][1], Al[mt][2], Al[mt][3],
                      aL + mt * 16 * ROWB + k0 * 32);
            }
            #pragma unroll
            for (int p = 0; p < 2; ++p) {           // ntile pairs (n0, n0+8)
                LDSM4(Bh[p][0], Bh[p][1], Bh[p][2], Bh[p][3],
                      bH + p * 16 * ROWB + k0 * 32);
                LDSM4(Bl[p][0], Bl[p][1], Bl[p][2], Bl[p][3],
                      bL + p * 16 * ROWB + k0 * 32);
            }
            #pragma unroll
            for (int mt = 0; mt < 4; ++mt)
                #pragma unroll
                for (int nt = 0; nt < 4; ++nt) {
                    uint32_t* bh = &Bh[nt >> 1][(nt & 1) * 2];
                    uint32_t* bl = &Bl[nt >> 1][(nt & 1) * 2];
                    MMA(acc[mt][nt], Ah[mt], bh);   // hi*hi
                    MMA(acc[mt][nt], Ah[mt], bl);   // hi*lo
                    MMA(acc[mt][nt], Al[mt], bh);   // lo*hi
                }
        }
        __syncthreads();
    }

    // ---- epilogue: bias + float2 stores ----
    const int gid = lane >> 2, qid = lane & 3;
    #pragma unroll
    for (int mt = 0; mt < 4; ++mt) {
        const int oc0 = ocBase + warp_m * 64 + mt * 16 + gid;
        const float bv0 = bias[oc0];
        const float bv1 = bias[oc0 + 8];
        #pragma unroll
        for (int nt = 0; nt < 4; ++nt) {
            const int p   = pixBase + warp_n * 32 + nt * 8 + qid * 2;
            const int b   = p / IMG;
            const int rem = p - b * IMG;
            float2 v0, v1;
            v0.x = acc[mt][nt][0] + bv0; v0.y = acc[mt][nt][1] + bv0;
            v1.x = acc[mt][nt][2] + bv1; v1.y = acc[mt][nt][3] + bv1;
            *(float2*)(out + ((size_t)(b * C_OUT + oc0)) * IMG + rem)     = v0;
            *(float2*)(out + ((size_t)(b * C_OUT + oc0 + 8)) * IMG + rem) = v1;
        }
    }
}

// ---------------- launch ----------------
extern "C" void kernel_launch(void* const* d_in, const int* in_sizes, int n_in,
                              void* d_out, int out_size) {
    const float* x    = (const float*)d_in[0];   // [32,128,56,56]
    const float* w    = (const float*)d_in[1];   // [256,128,3,3]
    const float* bias = (const float*)d_in[2];   // [256]
    float* out = (float*)d_out;                  // [32,256,56,56]

    xprep_kernel<<<dim3(NIMG, HW), 256>>>(x);
    wprep_kernel<<<(C_OUT * KTOT + 255) / 256, 256>>>(w);

    cudaFuncSetAttribute(conv_mma_kernel,
                         cudaFuncAttributeMaxDynamicSharedMemorySize, SMEM_TOTAL);
    conv_mma_kernel<<<dim3(NPIX / 128, C_OUT / 128), 256, SMEM_TOTAL>>>(bias, out);
}

// round 12
// speedup vs baseline: 3.6560x; 1.9886x over previous
#include <cuda_runtime.h>
#include <cuda_fp16.h>
#include <cstdint>

#define C_IN   128
#define C_OUT  256
#define HW     56
#define IMG    3136
#define NIMG   32
#define NPIX   100352
#define KTOT   1152          /* 9 taps * 128 ic */
#define NSTAGE 18            /* 9 taps * 2 (64-ic halves) */
#define ROWB   144           /* smem row stride: 128B data + 16B skew (conflict-free LDSM) */

// ---------------- device scratch (alloc-free) ----------------
__device__ __half g_xh[(size_t)NPIX * C_IN];   // NHWC fp16
__device__ __half g_wh[C_OUT * KTOT];          // [oc][tap][ic] fp16

// ---------------- PTX helpers (base PTX, OK on sm_103) ----------------
__device__ __forceinline__ uint32_t smem_u32(const void* p) {
    return (uint32_t)__cvta_generic_to_shared(p);
}
#define CP16(dst, src, sz) \
    asm volatile("cp.async.cg.shared.global [%0], [%1], 16, %2;" \
                 :: "r"(dst), "l"(src), "r"(sz))
#define CP_COMMIT() asm volatile("cp.async.commit_group;" ::: "memory")

#define LDSM4(r0, r1, r2, r3, a) \
    asm volatile("ldmatrix.sync.aligned.m8n8.x4.shared.b16 {%0,%1,%2,%3}, [%4];" \
                 : "=r"(r0), "=r"(r1), "=r"(r2), "=r"(r3) : "r"(a))

#define MMA(d, a, b) \
    asm volatile("mma.sync.aligned.m16n8k16.row.col.f32.f16.f16.f32 " \
                 "{%0,%1,%2,%3}, {%4,%5,%6,%7}, {%8,%9}, {%0,%1,%2,%3};" \
                 : "+f"((d)[0]), "+f"((d)[1]), "+f"((d)[2]), "+f"((d)[3]) \
                 : "r"((a)[0]), "r"((a)[1]), "r"((a)[2]), "r"((a)[3]), \
                   "r"((b)[0]), "r"((b)[1]))

// ---------------- SMEM layout: 3 pipeline buffers ----------------
// per stage: A (128 rows x 144B) + B (256 rows x 144B) = 55296 B
#define STG_A     18432
#define STG_BYTES 55296
#define SA_OFF(buf) ((buf) * STG_BYTES)
#define SB_OFF(buf) ((buf) * STG_BYTES + STG_A)
#define SMEM_TOTAL (3 * STG_BYTES)   /* 165888 */

// ---------------- prep kernels ----------------
__global__ void xprep_kernel(const float* __restrict__ x) {
    __shared__ float t[C_IN][HW + 1];
    const int b = blockIdx.x, h = blockIdx.y, tid = threadIdx.x;
    const float* src = x + ((size_t)b * C_IN) * IMG + h * HW;
    for (int i = tid; i < C_IN * HW; i += 256) {
        int ic = i / HW, w = i - ic * HW;
        t[ic][w] = src[(size_t)ic * IMG + w];
    }
    __syncthreads();
    const size_t ob = ((size_t)(b * HW + h) * HW) * C_IN;
    for (int i = tid; i < HW * (C_IN / 2); i += 256) {
        int w = i / (C_IN / 2), icp = (i - w * (C_IN / 2)) * 2;
        __half2 ph;
        ph.x = __float2half(t[icp][w]);
        ph.y = __float2half(t[icp + 1][w]);
        *(__half2*)&g_xh[ob + (size_t)w * C_IN + icp] = ph;
    }
}

__global__ void wprep_kernel(const float* __restrict__ w) {
    int i = blockIdx.x * 256 + threadIdx.x;           // dest-linear over 294912
    if (i < C_OUT * KTOT) {
        int oc = i / KTOT;
        int r = i - oc * KTOT;
        int tap = r >> 7, ic = r & 127;
        g_wh[i] = __float2half(w[(oc * C_IN + ic) * 9 + tap]);
    }
}

// ---------------- main MMA kernel ----------------
// CTA: 128 oc x 256 pix, K-chunk 64. 8 warps as 2(m) x 4(n); warp tile 64 x 64.
__global__ __launch_bounds__(256, 1)
void conv_mma_kernel(const float* __restrict__ bias, float* __restrict__ out) {
    extern __shared__ char smem[];
    const uint32_t sb = smem_u32(smem);
    const int tid = threadIdx.x;
    const int pixBase = blockIdx.x * 256;
    const int ocBase  = blockIdx.y * 128;

    // ---- loader geometry ----
    // A: thread pair per row (128 rows, 128B each): 4 x 16B chunks per thread
    const int arow = tid >> 1, ahalf = tid & 1;
    const char* aSrc = (const char*)(g_wh + (size_t)(ocBase + arow) * KTOT);
    const uint32_t aDstOff = (uint32_t)arow * ROWB + ahalf * 64;
    // B: one row (pixel) per thread (256 rows, 128B each): 8 x 16B chunks
    const int pg   = pixBase + tid;
    const int pb   = pg / IMG;
    const int prem = pg - pb * IMG;
    const int poh  = prem / HW;
    const int pow_ = prem - poh * HW;
    const size_t pbase = (size_t)pb * IMG;
    const uint32_t bDstOff = (uint32_t)tid * ROWB;

    auto load_stage = [&](int s) {
        const int buf = s % 3;
        const int tap = s >> 1, ich = (s & 1) << 6;   // 64-ic half
        const int tr = tap / 3, tc = tap - tr * 3;
        // A tile (weights)
        {
            const char* g = aSrc + ((tap << 7) + ich) * 2 + ahalf * 64;
            uint32_t d = sb + SA_OFF(buf) + aDstOff;
            #pragma unroll
            for (int i = 0; i < 4; ++i)
                CP16(d + i * 16, g + i * 16, 16);
        }
        // B tile (im2col pixels, zero-fill halo)
        {
            const int ih = poh + tr - 1, iw = pow_ + tc - 1;
            const bool ok = ((unsigned)ih < (unsigned)HW) && ((unsigned)iw < (unsigned)HW);
            const size_t gi = ok ? ((pbase + ih * HW + iw) * C_IN + ich) : 0;
            const int sz = ok ? 16 : 0;
            const char* g = (const char*)(g_xh + gi);
            uint32_t d = sb + SB_OFF(buf) + bDstOff;
            #pragma unroll
            for (int i = 0; i < 8; ++i)
                CP16(d + i * 16, g + i * 16, sz);
        }
        CP_COMMIT();
    };

    // ---- compute geometry ----
    const int wid = tid >> 5, lane = tid & 31;
    const int warp_m = wid >> 2;          // 0..1 -> 64 oc rows
    const int warp_n = wid & 3;           // 0..3 -> 64 pix cols
    const uint32_t aLaneOff =
        (uint32_t)(warp_m * 64 + (lane & 15)) * ROWB + (lane >> 4) * 16;
    const uint32_t bLaneOff =
        (uint32_t)(warp_n * 64 + ((lane >> 4) & 1) * 8 + (lane & 7)) * ROWB +
        ((lane >> 3) & 1) * 16;

    float acc[4][8][4];
    #pragma unroll
    for (int i = 0; i < 4; ++i)
        #pragma unroll
        for (int j = 0; j < 8; ++j)
            #pragma unroll
            for (int e = 0; e < 4; ++e) acc[i][j][e] = 0.f;

    load_stage(0);
    load_stage(1);

    for (int s = 0; s < NSTAGE; ++s) {
        if (s + 2 < NSTAGE) {
            load_stage(s + 2);
            asm volatile("cp.async.wait_group 2;" ::: "memory");
        } else if (s + 1 < NSTAGE) {
            asm volatile("cp.async.wait_group 1;" ::: "memory");
        } else {
            asm volatile("cp.async.wait_group 0;" ::: "memory");
        }
        __syncthreads();

        const int buf = s % 3;
        const uint32_t aP = sb + SA_OFF(buf) + aLaneOff;
        const uint32_t bP = sb + SB_OFF(buf) + bLaneOff;

        #pragma unroll
        for (int k0 = 0; k0 < 4; ++k0) {            // four k16 steps (32B apart)
            uint32_t A[4][4], B[4][4];
            #pragma unroll
            for (int mt = 0; mt < 4; ++mt)
                LDSM4(A[mt][0], A[mt][1], A[mt][2], A[mt][3],
                      aP + mt * 16 * ROWB + k0 * 32);
            #pragma unroll
            for (int p = 0; p < 4; ++p)             // nt pairs (2p, 2p+1)
                LDSM4(B[p][0], B[p][1], B[p][2], B[p][3],
                      bP + p * 16 * ROWB + k0 * 32);
            #pragma unroll
            for (int mt = 0; mt < 4; ++mt)
                #pragma unroll
                for (int nt = 0; nt < 8; ++nt) {
                    uint32_t* bf = &B[nt >> 1][(nt & 1) * 2];
                    MMA(acc[mt][nt], A[mt], bf);
                }
        }
        __syncthreads();
    }

    // ---- epilogue: bias + float2 stores ----
    const int gid = lane >> 2, qid = lane & 3;
    #pragma unroll
    for (int mt = 0; mt < 4; ++mt) {
        const int oc0 = ocBase + warp_m * 64 + mt * 16 + gid;
        const float bv0 = bias[oc0];
        const float bv1 = bias[oc0 + 8];
        #pragma unroll
        for (int nt = 0; nt < 8; ++nt) {
            const int p   = pixBase + warp_n * 64 + nt * 8 + qid * 2;
            const int b   = p / IMG;
            const int rem = p - b * IMG;
            float2 v0, v1;
            v0.x = acc[mt][nt][0] + bv0; v0.y = acc[mt][nt][1] + bv0;
            v1.x = acc[mt][nt][2] + bv1; v1.y = acc[mt][nt][3] + bv1;
            *(float2*)(out + ((size_t)(b * C_OUT + oc0)) * IMG + rem)     = v0;
            *(float2*)(out + ((size_t)(b * C_OUT + oc0 + 8)) * IMG + rem) = v1;
        }
    }
}

// ---------------- launch ----------------
extern "C" void kernel_launch(void* const* d_in, const int* in_sizes, int n_in,
                              void* d_out, int out_size) {
    const float* x    = (const float*)d_in[0];   // [32,128,56,56]
    const float* w    = (const float*)d_in[1];   // [256,128,3,3]
    const float* bias = (const float*)d_in[2];   // [256]
    float* out = (float*)d_out;                  // [32,256,56,56]

    xprep_kernel<<<dim3(NIMG, HW), 256>>>(x);
    wprep_kernel<<<(C_OUT * KTOT + 255) / 256, 256>>>(w);

    cudaFuncSetAttribute(conv_mma_kernel,
                         cudaFuncAttributeMaxDynamicSharedMemorySize, SMEM_TOTAL);
    conv_mma_kernel<<<dim3(NPIX / 256, C_OUT / 128), 256, SMEM_TOTAL>>>(bias, out);
}

// round 13
// speedup vs baseline: 4.2293x; 1.1568x over previous
#include <cuda_runtime.h>
#include <cuda_fp16.h>
#include <cstdint>

#define C_IN   128
#define C_OUT  256
#define HW     56
#define IMG    3136
#define NIMG   32
#define NPIX   100352
#define KTOT   1152          /* 9 taps * 128 ic */
#define NSTAGE 18            /* 9 taps * 2 (64-ic halves) */
#define ROWB   144           /* smem row stride: 128B data + 16B skew (conflict-free LDSM) */

// ---------------- device scratch (alloc-free) ----------------
__device__ __half g_xh[(size_t)NPIX * C_IN];   // NHWC fp16
__device__ __half g_wh[C_OUT * KTOT];          // [oc][tap][ic] fp16

// ---------------- PTX helpers (base PTX, OK on sm_103) ----------------
__device__ __forceinline__ uint32_t smem_u32(const void* p) {
    return (uint32_t)__cvta_generic_to_shared(p);
}
#define CP16(dst, src, sz) \
    asm volatile("cp.async.cg.shared.global [%0], [%1], 16, %2;" \
                 :: "r"(dst), "l"(src), "r"(sz))
#define CP_COMMIT() asm volatile("cp.async.commit_group;" ::: "memory")

#define LDSM4(r0, r1, r2, r3, a) \
    asm volatile("ldmatrix.sync.aligned.m8n8.x4.shared.b16 {%0,%1,%2,%3}, [%4];" \
                 : "=r"(r0), "=r"(r1), "=r"(r2), "=r"(r3) : "r"(a))

#define MMA(d, a, b) \
    asm volatile("mma.sync.aligned.m16n8k16.row.col.f32.f16.f16.f32 " \
                 "{%0,%1,%2,%3}, {%4,%5,%6,%7}, {%8,%9}, {%0,%1,%2,%3};" \
                 : "+f"((d)[0]), "+f"((d)[1]), "+f"((d)[2]), "+f"((d)[3]) \
                 : "r"((a)[0]), "r"((a)[1]), "r"((a)[2]), "r"((a)[3]), \
                   "r"((b)[0]), "r"((b)[1]))

// ---------------- SMEM layout: 2 pipeline buffers (occupancy 2) -----------
// per stage: A (128 rows x 144B) + B (128 rows x 144B) = 36864 B
#define STG_A     18432
#define STG_BYTES 36864
#define SA_OFF(buf) ((buf) * STG_BYTES)
#define SB_OFF(buf) ((buf) * STG_BYTES + STG_A)
#define SMEM_TOTAL (2 * STG_BYTES)   /* 73728 -> 2 CTAs/SM */

// ---------------- prep kernels ----------------
__global__ void xprep_kernel(const float* __restrict__ x) {
    __shared__ float t[C_IN][HW + 1];
    const int b = blockIdx.x, h = blockIdx.y, tid = threadIdx.x;
    const float* src = x + ((size_t)b * C_IN) * IMG + h * HW;
    for (int i = tid; i < C_IN * HW; i += 256) {
        int ic = i / HW, w = i - ic * HW;
        t[ic][w] = src[(size_t)ic * IMG + w];
    }
    __syncthreads();
    const size_t ob = ((size_t)(b * HW + h) * HW) * C_IN;
    for (int i = tid; i < HW * (C_IN / 2); i += 256) {
        int w = i / (C_IN / 2), icp = (i - w * (C_IN / 2)) * 2;
        __half2 ph;
        ph.x = __float2half(t[icp][w]);
        ph.y = __float2half(t[icp + 1][w]);
        *(__half2*)&g_xh[ob + (size_t)w * C_IN + icp] = ph;
    }
}

__global__ void wprep_kernel(const float* __restrict__ w) {
    int i = blockIdx.x * 256 + threadIdx.x;           // dest-linear over 294912
    if (i < C_OUT * KTOT) {
        int oc = i / KTOT;
        int r = i - oc * KTOT;
        int tap = r >> 7, ic = r & 127;
        g_wh[i] = __float2half(w[(oc * C_IN + ic) * 9 + tap]);
    }
}

// ---------------- main MMA kernel ----------------
// CTA: 128 oc x 128 pix, K-chunk 64. 8 warps as 2(m) x 4(n); warp tile 64 x 32.
// 2 CTAs/SM: sync/LDSM bubbles of one CTA covered by the other.
__global__ __launch_bounds__(256, 2)
void conv_mma_kernel(const float* __restrict__ bias, float* __restrict__ out) {
    extern __shared__ char smem[];
    const uint32_t sb = smem_u32(smem);
    const int tid = threadIdx.x;
    const int pixBase = blockIdx.x * 128;
    const int ocBase  = blockIdx.y * 128;

    // ---- loader geometry: thread pair per smem row, 4 x 16B per thread ----
    const int lrow = tid >> 1, half = tid & 1;
    const char* aSrc = (const char*)(g_wh + (size_t)(ocBase + lrow) * KTOT) + half * 64;
    const int pg   = pixBase + lrow;
    const int pb   = pg / IMG;
    const int prem = pg - pb * IMG;
    const int poh  = prem / HW;
    const int pow_ = prem - poh * HW;
    const size_t pbase = (size_t)pb * IMG;
    const uint32_t rowOff = (uint32_t)lrow * ROWB + half * 64;

    auto load_stage = [&](int s) {
        const int buf = s & 1;
        const int tap = s >> 1, ich = (s & 1) << 6;   // 64-ic half
        const int tr = tap / 3, tc = tap - tr * 3;
        // A tile (weights)
        {
            const char* g = aSrc + ((tap << 7) + ich) * 2;
            uint32_t d = sb + SA_OFF(buf) + rowOff;
            #pragma unroll
            for (int i = 0; i < 4; ++i)
                CP16(d + i * 16, g + i * 16, 16);
        }
        // B tile (im2col pixels, zero-fill halo)
        {
            const int ih = poh + tr - 1, iw = pow_ + tc - 1;
            const bool ok = ((unsigned)ih < (unsigned)HW) && ((unsigned)iw < (unsigned)HW);
            const size_t gi = ok ? ((pbase + ih * HW + iw) * C_IN + ich) : 0;
            const int sz = ok ? 16 : 0;
            const char* g = (const char*)(g_xh + gi) + half * 64;
            uint32_t d = sb + SB_OFF(buf) + rowOff;
            #pragma unroll
            for (int i = 0; i < 4; ++i)
                CP16(d + i * 16, g + i * 16, sz);
        }
        CP_COMMIT();
    };

    // ---- compute geometry ----
    const int wid = tid >> 5, lane = tid & 31;
    const int warp_m = wid >> 2;          // 0..1 -> 64 oc rows
    const int warp_n = wid & 3;           // 0..3 -> 32 pix cols
    const uint32_t aLaneOff =
        (uint32_t)(warp_m * 64 + (lane & 15)) * ROWB + (lane >> 4) * 16;
    const uint32_t bLaneOff =
        (uint32_t)(warp_n * 32 + ((lane >> 4) & 1) * 8 + (lane & 7)) * ROWB +
        ((lane >> 3) & 1) * 16;

    float acc[4][4][4];
    #pragma unroll
    for (int i = 0; i < 4; ++i)
        #pragma unroll
        for (int j = 0; j < 4; ++j)
            #pragma unroll
            for (int e = 0; e < 4; ++e) acc[i][j][e] = 0.f;

    load_stage(0);
    load_stage(1);

    for (int s = 0; s < NSTAGE; ++s) {
        asm volatile("cp.async.wait_group %0;" :: "n"(1) : "memory");
        if (s + 1 == NSTAGE)
            asm volatile("cp.async.wait_group 0;" ::: "memory");
        __syncthreads();

        const int buf = s & 1;
        const uint32_t aP = sb + SA_OFF(buf) + aLaneOff;
        const uint32_t bP = sb + SB_OFF(buf) + bLaneOff;

        #pragma unroll
        for (int k0 = 0; k0 < 4; ++k0) {            // four k16 steps (32B apart)
            uint32_t A[4][4], B[2][4];
            #pragma unroll
            for (int mt = 0; mt < 4; ++mt)
                LDSM4(A[mt][0], A[mt][1], A[mt][2], A[mt][3],
                      aP + mt * 16 * ROWB + k0 * 32);
            #pragma unroll
            for (int p = 0; p < 2; ++p)             // nt pairs (2p, 2p+1)
                LDSM4(B[p][0], B[p][1], B[p][2], B[p][3],
                      bP + p * 16 * ROWB + k0 * 32);
            #pragma unroll
            for (int mt = 0; mt < 4; ++mt)
                #pragma unroll
                for (int nt = 0; nt < 4; ++nt) {
                    uint32_t* bf = &B[nt >> 1][(nt & 1) * 2];
                    MMA(acc[mt][nt], A[mt], bf);
                }
        }
        __syncthreads();
        if (s + 2 < NSTAGE) load_stage(s + 2);      // buffer s&1 just freed
    }

    // ---- epilogue: bias + float2 stores ----
    const int gid = lane >> 2, qid = lane & 3;
    #pragma unroll
    for (int mt = 0; mt < 4; ++mt) {
        const int oc0 = ocBase + warp_m * 64 + mt * 16 + gid;
        const float bv0 = bias[oc0];
        const float bv1 = bias[oc0 + 8];
        #pragma unroll
        for (int nt = 0; nt < 4; ++nt) {
            const int p   = pixBase + warp_n * 32 + nt * 8 + qid * 2;
            const int b   = p / IMG;
            const int rem = p - b * IMG;
            float2 v0, v1;
            v0.x = acc[mt][nt][0] + bv0; v0.y = acc[mt][nt][1] + bv0;
            v1.x = acc[mt][nt][2] + bv1; v1.y = acc[mt][nt][3] + bv1;
            *(float2*)(out + ((size_t)(b * C_OUT + oc0)) * IMG + rem)     = v0;
            *(float2*)(out + ((size_t)(b * C_OUT + oc0 + 8)) * IMG + rem) = v1;
        }
    }
}

// ---------------- launch ----------------
extern "C" void kernel_launch(void* const* d_in, const int* in_sizes, int n_in,
                              void* d_out, int out_size) {
    const float* x    = (const float*)d_in[0];   // [32,128,56,56]
    const float* w    = (const float*)d_in[1];   // [256,128,3,3]
    const float* bias = (const float*)d_in[2];   // [256]
    float* out = (float*)d_out;                  // [32,256,56,56]

    xprep_kernel<<<dim3(NIMG, HW), 256>>>(x);
    wprep_kernel<<<(C_OUT * KTOT + 255) / 256, 256>>>(w);

    cudaFuncSetAttribute(conv_mma_kernel,
                         cudaFuncAttributeMaxDynamicSharedMemorySize, SMEM_TOTAL);
    conv_mma_kernel<<<dim3(NPIX / 128, C_OUT / 128), 256, SMEM_TOTAL>>>(bias, out);
}

// round 14
// speedup vs baseline: 4.4149x; 1.0439x over previous
#include <cuda_runtime.h>
#include <cuda_fp16.h>
#include <cstdint>

#define C_IN   128
#define C_OUT  256
#define HW     56
#define IMG    3136
#define NIMG   32
#define NPIX   100352
#define KTOT   1152          /* 9 taps * 128 ic */
#define NSTAGE 18            /* 9 taps * 2 (64-ic halves) */
#define ROWB   144           /* smem row stride: 128B data + 16B skew (conflict-free LDSM) */

// ---------------- device scratch (alloc-free) ----------------
__device__ __half g_xh[(size_t)NPIX * C_IN];   // NHWC fp16
__device__ __half g_wh[C_OUT * KTOT];          // [oc][tap][ic] fp16

// ---------------- PTX helpers (base PTX, OK on sm_103) ----------------
__device__ __forceinline__ uint32_t smem_u32(const void* p) {
    return (uint32_t)__cvta_generic_to_shared(p);
}
#define CP16(dst, src, sz) \
    asm volatile("cp.async.cg.shared.global [%0], [%1], 16, %2;" \
                 :: "r"(dst), "l"(src), "r"(sz))
#define CP_COMMIT() asm volatile("cp.async.commit_group;" ::: "memory")

#define LDSM4(r0, r1, r2, r3, a) \
    asm volatile("ldmatrix.sync.aligned.m8n8.x4.shared.b16 {%0,%1,%2,%3}, [%4];" \
                 : "=r"(r0), "=r"(r1), "=r"(r2), "=r"(r3) : "r"(a))

#define MMA(d, a, b) \
    asm volatile("mma.sync.aligned.m16n8k16.row.col.f32.f16.f16.f32 " \
                 "{%0,%1,%2,%3}, {%4,%5,%6,%7}, {%8,%9}, {%0,%1,%2,%3};" \
                 : "+f"((d)[0]), "+f"((d)[1]), "+f"((d)[2]), "+f"((d)[3]) \
                 : "r"((a)[0]), "r"((a)[1]), "r"((a)[2]), "r"((a)[3]), \
                   "r"((b)[0]), "r"((b)[1]))

// ---------------- SMEM layout: 3 pipeline buffers, occupancy 2 ------------
// per stage: A (128 rows x 144B) + B (128 rows x 144B) = 36864 B
#define STG_A     18432
#define STG_BYTES 36864
#define SA_OFF(buf) ((buf) * STG_BYTES)
#define SB_OFF(buf) ((buf) * STG_BYTES + STG_A)
#define SMEM_TOTAL (3 * STG_BYTES)   /* 110592 -> 2 CTAs/SM (221184 <= 228KB) */

// ---------------- fused prep kernel ----------------
// blocks [0, 1792): x -> NHWC fp16 ; blocks [1792, 1792+1152): w transpose
#define XBLKS 1792
#define WBLKS 1152
__global__ void prep_kernel(const float* __restrict__ x, const float* __restrict__ w) {
    const int blk = blockIdx.x, tid = threadIdx.x;
    if (blk < XBLKS) {
        __shared__ float t[C_IN][HW + 1];
        const int b = blk / HW, h = blk - (blk / HW) * HW;
        const float* src = x + ((size_t)b * C_IN) * IMG + h * HW;
        for (int i = tid; i < C_IN * HW; i += 256) {
            int ic = i / HW, ww = i - ic * HW;
            t[ic][ww] = src[(size_t)ic * IMG + ww];
        }
        __syncthreads();
        const size_t ob = ((size_t)(b * HW + h) * HW) * C_IN;
        for (int i = tid; i < HW * (C_IN / 2); i += 256) {
            int ww = i / (C_IN / 2), icp = (i - ww * (C_IN / 2)) * 2;
            __half2 ph;
            ph.x = __float2half(t[icp][ww]);
            ph.y = __float2half(t[icp + 1][ww]);
            *(__half2*)&g_xh[ob + (size_t)ww * C_IN + icp] = ph;
        }
    } else {
        int i = (blk - XBLKS) * 256 + tid;          // dest-linear over 294912
        if (i < C_OUT * KTOT) {
            int oc = i / KTOT;
            int r = i - oc * KTOT;
            int tap = r >> 7, ic = r & 127;
            g_wh[i] = __float2half(w[(oc * C_IN + ic) * 9 + tap]);
        }
    }
}

// ---------------- main MMA kernel ----------------
// CTA: 128 oc x 128 pix, K-chunk 64. 8 warps as 2(m) x 4(n); warp tile 64 x 32.
// 3-stage cp.async pipeline, ONE __syncthreads per stage, 2 CTAs/SM.
__global__ __launch_bounds__(256, 2)
void conv_mma_kernel(const float* __restrict__ bias, float* __restrict__ out) {
    extern __shared__ char smem[];
    const uint32_t sb = smem_u32(smem);
    const int tid = threadIdx.x;
    const int pixBase = blockIdx.x * 128;
    const int ocBase  = blockIdx.y * 128;

    // ---- loader geometry: thread pair per smem row, 4 x 16B per thread ----
    const int lrow = tid >> 1, half = tid & 1;
    const char* aSrc = (const char*)(g_wh + (size_t)(ocBase + lrow) * KTOT) + half * 64;
    const int pg   = pixBase + lrow;
    const int pb   = pg / IMG;
    const int prem = pg - pb * IMG;
    const int poh  = prem / HW;
    const int pow_ = prem - poh * HW;
    const size_t pbase = (size_t)pb * IMG;
    const uint32_t rowOff = (uint32_t)lrow * ROWB + half * 64;

    auto load_stage = [&](int s) {
        const int buf = s % 3;
        const int tap = s >> 1, ich = (s & 1) << 6;   // 64-ic half
        const int tr = tap / 3, tc = tap - tr * 3;
        // A tile (weights)
        {
            const char* g = aSrc + ((tap << 7) + ich) * 2;
            uint32_t d = sb + SA_OFF(buf) + rowOff;
            #pragma unroll
            for (int i = 0; i < 4; ++i)
                CP16(d + i * 16, g + i * 16, 16);
        }
        // B tile (im2col pixels, zero-fill halo)
        {
            const int ih = poh + tr - 1, iw = pow_ + tc - 1;
            const bool ok = ((unsigned)ih < (unsigned)HW) && ((unsigned)iw < (unsigned)HW);
            const size_t gi = ok ? ((pbase + ih * HW + iw) * C_IN + ich) : 0;
            const int sz = ok ? 16 : 0;
            const char* g = (const char*)(g_xh + gi) + half * 64;
            uint32_t d = sb + SB_OFF(buf) + rowOff;
            #pragma unroll
            for (int i = 0; i < 4; ++i)
                CP16(d + i * 16, g + i * 16, sz);
        }
        CP_COMMIT();
    };

    // ---- compute geometry ----
    const int wid = tid >> 5, lane = tid & 31;
    const int warp_m = wid >> 2;          // 0..1 -> 64 oc rows
    const int warp_n = wid & 3;           // 0..3 -> 32 pix cols
    const uint32_t aLaneOff =
        (uint32_t)(warp_m * 64 + (lane & 15)) * ROWB + (lane >> 4) * 16;
    const uint32_t bLaneOff =
        (uint32_t)(warp_n * 32 + ((lane >> 4) & 1) * 8 + (lane & 7)) * ROWB +
        ((lane >> 3) & 1) * 16;

    float acc[4][4][4];
    #pragma unroll
    for (int i = 0; i < 4; ++i)
        #pragma unroll
        for (int j = 0; j < 4; ++j)
            #pragma unroll
            for (int e = 0; e < 4; ++e) acc[i][j][e] = 0.f;

    load_stage(0);
    load_stage(1);

    for (int s = 0; s < NSTAGE; ++s) {
        // stage s arrived? (allow 1 newer group outstanding; 0 at the tail)
        if (s + 1 < NSTAGE)
            asm volatile("cp.async.wait_group 1;" ::: "memory");
        else
            asm volatile("cp.async.wait_group 0;" ::: "memory");
        __syncthreads();   // data visible + buf (s+2)%3 free (computed in s-1)

        if (s + 2 < NSTAGE) load_stage(s + 2);

        const int buf = s % 3;
        const uint32_t aP = sb + SA_OFF(buf) + aLaneOff;
        const uint32_t bP = sb + SB_OFF(buf) + bLaneOff;

        #pragma unroll
        for (int k0 = 0; k0 < 4; ++k0) {            // four k16 steps (32B apart)
            uint32_t A[4][4], B[2][4];
            #pragma unroll
            for (int mt = 0; mt < 4; ++mt)
                LDSM4(A[mt][0], A[mt][1], A[mt][2], A[mt][3],
                      aP + mt * 16 * ROWB + k0 * 32);
            #pragma unroll
            for (int p = 0; p < 2; ++p)             // nt pairs (2p, 2p+1)
                LDSM4(B[p][0], B[p][1], B[p][2], B[p][3],
                      bP + p * 16 * ROWB + k0 * 32);
            #pragma unroll
            for (int mt = 0; mt < 4; ++mt)
                #pragma unroll
                for (int nt = 0; nt < 4; ++nt) {
                    uint32_t* bf = &B[nt >> 1][(nt & 1) * 2];
                    MMA(acc[mt][nt], A[mt], bf);
                }
        }
    }

    // ---- epilogue: bias + float2 stores ----
    const int gid = lane >> 2, qid = lane & 3;
    #pragma unroll
    for (int mt = 0; mt < 4; ++mt) {
        const int oc0 = ocBase + warp_m * 64 + mt * 16 + gid;
        const float bv0 = bias[oc0];
        const float bv1 = bias[oc0 + 8];
        #pragma unroll
        for (int nt = 0; nt < 4; ++nt) {
            const int p   = pixBase + warp_n * 32 + nt * 8 + qid * 2;
            const int b   = p / IMG;
            const int rem = p - b * IMG;
            float2 v0, v1;
            v0.x = acc[mt][nt][0] + bv0; v0.y = acc[mt][nt][1] + bv0;
            v1.x = acc[mt][nt][2] + bv1; v1.y = acc[mt][nt][3] + bv1;
            *(float2*)(out + ((size_t)(b * C_OUT + oc0)) * IMG + rem)     = v0;
            *(float2*)(out + ((size_t)(b * C_OUT + oc0 + 8)) * IMG + rem) = v1;
        }
    }
}

// ---------------- launch ----------------
extern "C" void kernel_launch(void* const* d_in, const int* in_sizes, int n_in,
                              void* d_out, int out_size) {
    const float* x    = (const float*)d_in[0];   // [32,128,56,56]
    const float* w    = (const float*)d_in[1];   // [256,128,3,3]
    const float* bias = (const float*)d_in[2];   // [256]
    float* out = (float*)d_out;                  // [32,256,56,56]

    prep_kernel<<<XBLKS + WBLKS, 256>>>(x, w);

    cudaFuncSetAttribute(conv_mma_kernel,
                         cudaFuncAttributeMaxDynamicSharedMemorySize, SMEM_TOTAL);
    conv_mma_kernel<<<dim3(NPIX / 128, C_OUT / 128), 256, SMEM_TOTAL>>>(bias, out);
}

// round 15
// speedup vs baseline: 6.0823x; 1.3777x over previous
#include <cuda_runtime.h>
#include <cuda_fp16.h>
#include <cstdint>

#define C_IN   128
#define C_OUT  256
#define HW     56
#define IMG    3136
#define NIMG   32
#define KTOT   1152          /* 9 taps * 128 ic */
#define ROWB   144           /* smem row stride: 128B data + 16B skew */

#define TH     8             /* output rows per CTA */
#define TW     32            /* output cols per CTA (w padded to 64: 2 tiles) */
#define EXTW   34            /* TW + 2 halo */
#define EXTH   10            /* TH + 2 halo */
#define EXTROWS (EXTH * EXTW)   /* 340 */
#define NSUB   18            /* 2 ic-halves * 9 taps */

// ---------------- device scratch (alloc-free) ----------------
__device__ __half g_xh[(size_t)NIMG * IMG * C_IN];   // NHWC fp16
__device__ __half g_wh[C_OUT * KTOT];                // [oc][tap][ic] fp16

// ---------------- PTX helpers (base PTX, OK on sm_103) ----------------
__device__ __forceinline__ uint32_t smem_u32(const void* p) {
    return (uint32_t)__cvta_generic_to_shared(p);
}
#define CP16(dst, src, sz) \
    asm volatile("cp.async.cg.shared.global [%0], [%1], 16, %2;" \
                 :: "r"(dst), "l"(src), "r"(sz))
#define CP_COMMIT() asm volatile("cp.async.commit_group;" ::: "memory")

#define LDSM4(r0, r1, r2, r3, a) \
    asm volatile("ldmatrix.sync.aligned.m8n8.x4.shared.b16 {%0,%1,%2,%3}, [%4];" \
                 : "=r"(r0), "=r"(r1), "=r"(r2), "=r"(r3) : "r"(a))

#define MMA(d, a, b) \
    asm volatile("mma.sync.aligned.m16n8k16.row.col.f32.f16.f16.f32 " \
                 "{%0,%1,%2,%3}, {%4,%5,%6,%7}, {%8,%9}, {%0,%1,%2,%3};" \
                 : "+f"((d)[0]), "+f"((d)[1]), "+f"((d)[2]), "+f"((d)[3]) \
                 : "r"((a)[0]), "r"((a)[1]), "r"((a)[2]), "r"((a)[3]), \
                   "r"((b)[0]), "r"((b)[1]))

// ---------------- SMEM layout ----------------
// A substage: 128 oc rows x 144B (64 ic = 128B data). 3 buffers.
// B halo tile: 340 rows x 144B. 2 resident (one per ic-half).
#define SA_BYTES (128 * ROWB)          /* 18432 */
#define SB_BYTES (EXTROWS * ROWB)      /* 48960 */
#define SA_OFF(b) ((b) * SA_BYTES)
#define SB_OFF(i) (3 * SA_BYTES + (i) * SB_BYTES)
#define SMEM_TOTAL (3 * SA_BYTES + 2 * SB_BYTES)   /* 153216 */

// ---------------- fused prep kernel ----------------
#define XBLKS 1792
#define WBLKS 1152
__global__ void prep_kernel(const float* __restrict__ x, const float* __restrict__ w) {
    const int blk = blockIdx.x, tid = threadIdx.x;
    if (blk < XBLKS) {
        __shared__ float t[C_IN][HW + 1];
        const int b = blk / HW, h = blk - (blk / HW) * HW;
        const float* src = x + ((size_t)b * C_IN) * IMG + h * HW;
        for (int i = tid; i < C_IN * HW; i += 256) {
            int ic = i / HW, ww = i - ic * HW;
            t[ic][ww] = src[(size_t)ic * IMG + ww];
        }
        __syncthreads();
        const size_t ob = ((size_t)(b * HW + h) * HW) * C_IN;
        for (int i = tid; i < HW * (C_IN / 2); i += 256) {
            int ww = i / (C_IN / 2), icp = (i - ww * (C_IN / 2)) * 2;
            __half2 ph;
            ph.x = __float2half(t[icp][ww]);
            ph.y = __float2half(t[icp + 1][ww]);
            *(__half2*)&g_xh[ob + (size_t)ww * C_IN + icp] = ph;
        }
    } else {
        int i = (blk - XBLKS) * 256 + tid;
        if (i < C_OUT * KTOT) {
            int oc = i / KTOT;
            int r = i - oc * KTOT;
            int tap = r >> 7, ic = r & 127;
            g_wh[i] = __float2half(w[(oc * C_IN + ic) * 9 + tap]);
        }
    }
}

// ---------------- main MMA kernel ----------------
// CTA: 128 oc x 256 pix (8h x 32w of one image). 512 thr, warps 4(m) x 4(n).
// B loaded ONCE per 64-ic half (haloed 10x34 tile) and reused by all 9 taps.
__global__ __launch_bounds__(512, 1)
void conv_mma_kernel(const float* __restrict__ bias, float* __restrict__ out) {
    extern __shared__ char smem[];
    const uint32_t sb = smem_u32(smem);
    const int tid = threadIdx.x;
    const int bx  = blockIdx.x;
    const int img = bx / 14;
    const int rr  = bx - img * 14;
    const int h0  = (rr >> 1) * TH;
    const int w0  = (rr & 1) * TW;
    const int ocBase = blockIdx.y * 128;

    // ---- loaders ----
    auto load_A = [&](int tap, int ich, int buf) {
        #pragma unroll
        for (int t = 0; t < 2; ++t) {
            const int i = tid + t * 512;           // 1024 slots: 128 rows x 8 chunks
            const int row = i >> 3, ch = i & 7;
            const char* g = (const char*)(g_wh + (size_t)(ocBase + row) * KTOT
                                          + tap * C_IN + (ich << 6)) + ch * 16;
            const uint32_t d = sb + SA_OFF(buf) + (uint32_t)row * ROWB + ch * 16;
            CP16(d, g, 16);
        }
    };
    auto load_B = [&](int ich) {
        const size_t ibase = (size_t)img * IMG;
        for (int i = tid; i < EXTROWS * 8; i += 512) {     // 2720 slots
            const int row = i >> 3, ch = i & 7;
            const int eh = row / EXTW, ew = row - eh * EXTW;
            const int ih = h0 - 1 + eh, iw = w0 - 1 + ew;
            const bool ok = ((unsigned)ih < (unsigned)HW) && ((unsigned)iw < (unsigned)HW);
            const size_t gi = ok ? ((ibase + ih * HW + iw) * C_IN + (ich << 6)) : 0;
            const char* g = (const char*)(g_xh + gi) + ch * 16;
            const uint32_t d = sb + SB_OFF(ich) + (uint32_t)row * ROWB + ch * 16;
            CP16(d, g, ok ? 16 : 0);
        }
    };

    // ---- compute geometry ----
    const int wid = tid >> 5, lane = tid & 31;
    const int warp_m = wid >> 2;          // 0..3 -> 32 oc rows
    const int warp_n = wid & 3;           // 0..3 -> 64 pix (2 dh x 32 dw)
    const uint32_t aLane =
        (uint32_t)(warp_m * 32 + (lane & 15)) * ROWB + (lane >> 4) * 16;
    const uint32_t bLane =
        (uint32_t)(((lane >> 4) & 1) * 8 + (lane & 7)) * ROWB + ((lane >> 3) & 1) * 16;

    float acc[2][8][4];
    #pragma unroll
    for (int i = 0; i < 2; ++i)
        #pragma unroll
        for (int j = 0; j < 8; ++j)
            #pragma unroll
            for (int e = 0; e < 4; ++e) acc[i][j][e] = 0.f;

    // ---- prologue: g0={B0,A0}, g1={A1}, g2={B1} ----
    load_B(0); load_A(0, 0, 0); CP_COMMIT();
    load_A(1, 0, 1);            CP_COMMIT();
    load_B(1);                  CP_COMMIT();

    int s = 0;
    int pf_tap = 2, pf_ich = 0;   // next A substage to prefetch (s+2)
    #pragma unroll 1
    for (int ich = 0; ich < 2; ++ich) {
        #pragma unroll 1
        for (int tap = 0; tap < 9; ++tap, ++s) {
            if (s <= 15)      asm volatile("cp.async.wait_group 2;" ::: "memory");
            else if (s == 16) asm volatile("cp.async.wait_group 1;" ::: "memory");
            else              asm volatile("cp.async.wait_group 0;" ::: "memory");
            __syncthreads();   // data for s visible; buffer (s+2)%3 free

            if (s <= 15) {
                load_A(pf_tap, pf_ich, (s + 2) % 3);
                CP_COMMIT();
                if (++pf_tap == 9) { pf_tap = 0; pf_ich = 1; }
            }

            const int tr = tap / 3;
            const int tc = tap - tr * 3;
            const uint32_t aP = sb + SA_OFF(s % 3) + aLane;
            const uint32_t bP = sb + SB_OFF(ich) +
                (uint32_t)((warp_n * 2 + tr) * EXTW + tc) * ROWB + bLane;

            #pragma unroll
            for (int k0 = 0; k0 < 4; ++k0) {
                uint32_t A[2][4], B[4][4];
                #pragma unroll
                for (int mt = 0; mt < 2; ++mt)
                    LDSM4(A[mt][0], A[mt][1], A[mt][2], A[mt][3],
                          aP + mt * 16 * ROWB + k0 * 32);
                #pragma unroll
                for (int p = 0; p < 4; ++p)
                    LDSM4(B[p][0], B[p][1], B[p][2], B[p][3],
                          bP + (uint32_t)(((p >> 1) * EXTW + (p & 1) * 16) * ROWB)
                             + k0 * 32);
                #pragma unroll
                for (int mt = 0; mt < 2; ++mt)
                    #pragma unroll
                    for (int nt = 0; nt < 8; ++nt) {
                        uint32_t* bf = &B[nt >> 1][(nt & 1) * 2];
                        MMA(acc[mt][nt], A[mt], bf);
                    }
            }
        }
    }

    // ---- epilogue: bias + guarded float2 stores ----
    const int gid = lane >> 2, qid = lane & 3;
    #pragma unroll
    for (int mt = 0; mt < 2; ++mt) {
        const int oc0 = ocBase + warp_m * 32 + mt * 16 + gid;
        const float bv0 = bias[oc0];
        const float bv1 = bias[oc0 + 8];
        #pragma unroll
        for (int nt = 0; nt < 8; ++nt) {
            const int dh = warp_n * 2 + (nt >> 2);
            const int dw = ((nt >> 1) & 1) * 16 + (nt & 1) * 8 + qid * 2;
            if (w0 + dw < HW) {
                float* dst = out + ((size_t)(img * C_OUT + oc0)) * IMG
                             + (h0 + dh) * HW + (w0 + dw);
                float2 v0, v1;
                v0.x = acc[mt][nt][0] + bv0; v0.y = acc[mt][nt][1] + bv0;
                v1.x = acc[mt][nt][2] + bv1; v1.y = acc[mt][nt][3] + bv1;
                *(float2*)dst = v0;
                *(float2*)(dst + 8 * IMG) = v1;
            }
        }
    }
}

// ---------------- launch ----------------
extern "C" void kernel_launch(void* const* d_in, const int* in_sizes, int n_in,
                              void* d_out, int out_size) {
    const float* x    = (const float*)d_in[0];   // [32,128,56,56]
    const float* w    = (const float*)d_in[1];   // [256,128,3,3]
    const float* bias = (const float*)d_in[2];   // [256]
    float* out = (float*)d_out;                  // [32,256,56,56]

    prep_kernel<<<XBLKS + WBLKS, 256>>>(x, w);

    cudaFuncSetAttribute(conv_mma_kernel,
                         cudaFuncAttributeMaxDynamicSharedMemorySize, SMEM_TOTAL);
    conv_mma_kernel<<<dim3(NIMG * 14, 2), 512, SMEM_TOTAL>>>(bias, out);
}

// round 16
// speedup vs baseline: 6.0976x; 1.0025x over previous
#include <cuda_runtime.h>
#include <cuda_fp16.h>
#include <cstdint>

#define C_IN   128
#define C_OUT  256
#define HW     56
#define IMG    3136
#define NIMG   32
#define KTOT   1152          /* 9 taps * 128 ic */
#define ROWB   144           /* smem row stride: 128B data + 16B skew */

#define TH     8             /* output rows per CTA */
#define TW     32            /* output cols per CTA (w padded to 64: 2 tiles) */
#define EXTW   34            /* TW + 2 halo */
#define EXTH   10            /* TH + 2 halo */
#define EXTROWS (EXTH * EXTW)   /* 340 */

// ---------------- device scratch (alloc-free) ----------------
__device__ __half g_xh[(size_t)NIMG * IMG * C_IN];   // NHWC fp16
__device__ __half g_wh[C_OUT * KTOT];                // [oc][tap][ic] fp16

// ---------------- PTX helpers (base PTX, OK on sm_103) ----------------
__device__ __forceinline__ uint32_t smem_u32(const void* p) {
    return (uint32_t)__cvta_generic_to_shared(p);
}
#define CP16(dst, src, sz) \
    asm volatile("cp.async.cg.shared.global [%0], [%1], 16, %2;" \
                 :: "r"(dst), "l"(src), "r"(sz))
#define CP_COMMIT() asm volatile("cp.async.commit_group;" ::: "memory")

#define LDSM4(r0, r1, r2, r3, a) \
    asm volatile("ldmatrix.sync.aligned.m8n8.x4.shared.b16 {%0,%1,%2,%3}, [%4];" \
                 : "=r"(r0), "=r"(r1), "=r"(r2), "=r"(r3) : "r"(a))

#define MMA(d, a, b) \
    asm volatile("mma.sync.aligned.m16n8k16.row.col.f32.f16.f16.f32 " \
                 "{%0,%1,%2,%3}, {%4,%5,%6,%7}, {%8,%9}, {%0,%1,%2,%3};" \
                 : "+f"((d)[0]), "+f"((d)[1]), "+f"((d)[2]), "+f"((d)[3]) \
                 : "r"((a)[0]), "r"((a)[1]), "r"((a)[2]), "r"((a)[3]), \
                   "r"((b)[0]), "r"((b)[1]))

// ---------------- SMEM layout ----------------
#define SA_BYTES (128 * ROWB)          /* 18432 */
#define SB_BYTES (EXTROWS * ROWB)      /* 48960 */
#define SA_OFF(b) ((b) * SA_BYTES)
#define SB_OFF(i) (3 * SA_BYTES + (i) * SB_BYTES)
#define SMEM_TOTAL (3 * SA_BYTES + 2 * SB_BYTES)   /* 153216 */

// ---------------- fused prep kernel ----------------
#define XBLKS 1792
#define WBLKS 1152
__global__ void prep_kernel(const float* __restrict__ x, const float* __restrict__ w) {
    const int blk = blockIdx.x, tid = threadIdx.x;
    if (blk < XBLKS) {
        __shared__ float t[C_IN][HW + 1];
        const int b = blk / HW, h = blk - (blk / HW) * HW;
        const float* src = x + ((size_t)b * C_IN) * IMG + h * HW;
        for (int i = tid; i < C_IN * HW; i += 256) {
            int ic = i / HW, ww = i - ic * HW;
            t[ic][ww] = src[(size_t)ic * IMG + ww];
        }
        __syncthreads();
        // write: 16 threads per pixel, 8 ic each -> uint4 (16B) stores
        const size_t ob = ((size_t)(b * HW + h) * HW) * C_IN;
        for (int i = tid; i < HW * 16; i += 256) {
            const int ww = i >> 4, grp = (i & 15) * 8;
            __half h8[8];
            #pragma unroll
            for (int e = 0; e < 8; ++e) h8[e] = __float2half(t[grp + e][ww]);
            *(uint4*)&g_xh[ob + (size_t)ww * C_IN + grp] = *(uint4*)h8;
        }
    } else {
        int i = (blk - XBLKS) * 256 + tid;
        if (i < C_OUT * KTOT) {
            int oc = i / KTOT;
            int r = i - oc * KTOT;
            int tap = r >> 7, ic = r & 127;
            g_wh[i] = __float2half(w[(oc * C_IN + ic) * 9 + tap]);
        }
    }
}

// ---------------- main MMA kernel ----------------
// CTA: 128 oc x 256 pix (8h x 32w of one image). 256 thr, 8 warps 2(m) x 4(n).
// Warp tile 64 oc x 64 pix -> LDSM:MMA ratio 0.25, 256-reg budget for pipelining.
__global__ __launch_bounds__(256, 1)
void conv_mma_kernel(const float* __restrict__ bias, float* __restrict__ out) {
    extern __shared__ char smem[];
    const uint32_t sb = smem_u32(smem);
    const int tid = threadIdx.x;
    const int bx  = blockIdx.x;
    const int img = bx / 14;
    const int rr  = bx - img * 14;
    const int h0  = (rr >> 1) * TH;
    const int w0  = (rr & 1) * TW;
    const int ocBase = blockIdx.y * 128;

    // ---- loaders (256 threads) ----
    auto load_A = [&](int tap, int ich, int buf) {
        #pragma unroll
        for (int t = 0; t < 4; ++t) {
            const int i = tid + t * 256;           // 1024 slots: 128 rows x 8 chunks
            const int row = i >> 3, ch = i & 7;
            const char* g = (const char*)(g_wh + (size_t)(ocBase + row) * KTOT
                                          + tap * C_IN + (ich << 6)) + ch * 16;
            const uint32_t d = sb + SA_OFF(buf) + (uint32_t)row * ROWB + ch * 16;
            CP16(d, g, 16);
        }
    };
    auto load_B = [&](int ich) {
        const size_t ibase = (size_t)img * IMG;
        for (int i = tid; i < EXTROWS * 8; i += 256) {     // 2720 slots
            const int row = i >> 3, ch = i & 7;
            const int eh = row / EXTW, ew = row - eh * EXTW;
            const int ih = h0 - 1 + eh, iw = w0 - 1 + ew;
            const bool ok = ((unsigned)ih < (unsigned)HW) && ((unsigned)iw < (unsigned)HW);
            const size_t gi = ok ? ((ibase + ih * HW + iw) * C_IN + (ich << 6)) : 0;
            const char* g = (const char*)(g_xh + gi) + ch * 16;
            const uint32_t d = sb + SB_OFF(ich) + (uint32_t)row * ROWB + ch * 16;
            CP16(d, g, ok ? 16 : 0);
        }
    };

    // ---- compute geometry ----
    const int wid = tid >> 5, lane = tid & 31;
    const int warp_m = wid >> 2;          // 0..1 -> 64 oc rows
    const int warp_n = wid & 3;           // 0..3 -> 64 pix (2 dh x 32 dw)
    const uint32_t aLane =
        (uint32_t)(warp_m * 64 + (lane & 15)) * ROWB + (lane >> 4) * 16;
    const uint32_t bLane =
        (uint32_t)(((lane >> 4) & 1) * 8 + (lane & 7)) * ROWB + ((lane >> 3) & 1) * 16;

    float acc[4][8][4];
    #pragma unroll
    for (int i = 0; i < 4; ++i)
        #pragma unroll
        for (int j = 0; j < 8; ++j)
            #pragma unroll
            for (int e = 0; e < 4; ++e) acc[i][j][e] = 0.f;

    // ---- prologue: g0={B0,A0}, g1={A1}, g2={B1} ----
    load_B(0); load_A(0, 0, 0); CP_COMMIT();
    load_A(1, 0, 1);            CP_COMMIT();
    load_B(1);                  CP_COMMIT();

    int s = 0;
    int pf_tap = 2, pf_ich = 0;   // next A substage to prefetch (s+2)
    #pragma unroll 1
    for (int ich = 0; ich < 2; ++ich) {
        #pragma unroll 1
        for (int tap = 0; tap < 9; ++tap, ++s) {
            if (s <= 15)      asm volatile("cp.async.wait_group 2;" ::: "memory");
            else if (s == 16) asm volatile("cp.async.wait_group 1;" ::: "memory");
            else              asm volatile("cp.async.wait_group 0;" ::: "memory");
            __syncthreads();   // data for s visible; buffer (s+2)%3 free

            if (s <= 15) {
                load_A(pf_tap, pf_ich, (s + 2) % 3);
                CP_COMMIT();
                if (++pf_tap == 9) { pf_tap = 0; pf_ich = 1; }
            }

            const int tr = tap / 3;
            const int tc = tap - tr * 3;
            const uint32_t aP = sb + SA_OFF(s % 3) + aLane;
            const uint32_t bP = sb + SB_OFF(ich) +
                (uint32_t)((warp_n * 2 + tr) * EXTW + tc) * ROWB + bLane;

            #pragma unroll
            for (int k0 = 0; k0 < 4; ++k0) {
                uint32_t A[4][4], B[4][4];
                #pragma unroll
                for (int mt = 0; mt < 4; ++mt)
                    LDSM4(A[mt][0], A[mt][1], A[mt][2], A[mt][3],
                          aP + mt * 16 * ROWB + k0 * 32);
                #pragma unroll
                for (int p = 0; p < 4; ++p)
                    LDSM4(B[p][0], B[p][1], B[p][2], B[p][3],
                          bP + (uint32_t)(((p >> 1) * EXTW + (p & 1) * 16) * ROWB)
                             + k0 * 32);
                #pragma unroll
                for (int mt = 0; mt < 4; ++mt)
                    #pragma unroll
                    for (int nt = 0; nt < 8; ++nt) {
                        uint32_t* bf = &B[nt >> 1][(nt & 1) * 2];
                        MMA(acc[mt][nt], A[mt], bf);
                    }
            }
        }
    }

    // ---- epilogue: bias + guarded float2 stores ----
    const int gid = lane >> 2, qid = lane & 3;
    #pragma unroll
    for (int mt = 0; mt < 4; ++mt) {
        const int oc0 = ocBase + warp_m * 64 + mt * 16 + gid;
        const float bv0 = bias[oc0];
        const float bv1 = bias[oc0 + 8];
        #pragma unroll
        for (int nt = 0; nt < 8; ++nt) {
            const int dh = warp_n * 2 + (nt >> 2);
            const int dw = ((nt >> 1) & 1) * 16 + (nt & 1) * 8 + qid * 2;
            if (w0 + dw < HW) {
                float* dst = out + ((size_t)(img * C_OUT + oc0)) * IMG
                             + (h0 + dh) * HW + (w0 + dw);
                float2 v0, v1;
                v0.x = acc[mt][nt][0] + bv0; v0.y = acc[mt][nt][1] + bv0;
                v1.x = acc[mt][nt][2] + bv1; v1.y = acc[mt][nt][3] + bv1;
                *(float2*)dst = v0;
                *(float2*)(dst + 8 * IMG) = v1;
            }
        }
    }
}

// ---------------- launch ----------------
extern "C" void kernel_launch(void* const* d_in, const int* in_sizes, int n_in,
                              void* d_out, int out_size) {
    const float* x    = (const float*)d_in[0];   // [32,128,56,56]
    const float* w    = (const float*)d_in[1];   // [256,128,3,3]
    const float* bias = (const float*)d_in[2];   // [256]
    float* out = (float*)d_out;                  // [32,256,56,56]

    prep_kernel<<<XBLKS + WBLKS, 256>>>(x, w);

    cudaFuncSetAttribute(conv_mma_kernel,
                         cudaFuncAttributeMaxDynamicSharedMemorySize, SMEM_TOTAL);
    conv_mma_kernel<<<dim3(NIMG * 14, 2), 256, SMEM_TOTAL>>>(bias, out);
}